// round 6
// baseline (speedup 1.0000x reference)
#include <cuda_runtime.h>

// Problem constants (fixed by the reference): B=4, S=2048, E=16, H=4, D_K=4
#define BB 4
#define SS 2048
#define EE 16
#define HH 4
#define DK 4
#define NBH (BB*HH)

#define KSPLIT 16
#define KT (SS/KSPLIT)       // 128 keys per split tile
#define THREADS 128
#define QBLK THREADS         // 128 queries per CTA (1 per thread)
#define PSTRIDE (BB*SS*HH)   // partial-array stride per split (float4 / scalar units)

typedef unsigned long long u64;

// Scratch (allocation-free rule: __device__ globals)
__device__ float g_parta[KSPLIT * BB * SS * EE];   // partial unnormalized attn out
__device__ float g_partl[KSPLIT * BB * SS * HH];   // partial softmax denominators

__device__ __forceinline__ float ex2f(float x) {
    float y; asm("ex2.approx.ftz.f32 %0, %1;" : "=f"(y) : "f"(x)); return y;
}
__device__ __forceinline__ u64 pk2(float lo, float hi) {
    u64 r; asm("mov.b64 %0, {%1, %2};" : "=l"(r) : "f"(lo), "f"(hi)); return r;
}
__device__ __forceinline__ void upk2(u64 v, float& lo, float& hi) {
    asm("mov.b64 {%0, %1}, %2;" : "=f"(lo), "=f"(hi) : "l"(v));
}
__device__ __forceinline__ u64 fma2(u64 a, u64 b, u64 c) {
    u64 d; asm("fma.rn.f32x2 %0, %1, %2, %3;" : "=l"(d) : "l"(a), "l"(b), "l"(c)); return d;
}
__device__ __forceinline__ u64 mul2(u64 a, u64 b) {
    u64 d; asm("mul.rn.f32x2 %0, %1, %2;" : "=l"(d) : "l"(a), "l"(b)); return d;
}
__device__ __forceinline__ u64 add2(u64 a, u64 b) {
    u64 d; asm("add.rn.f32x2 %0, %1, %2;" : "=l"(d) : "l"(a), "l"(b)); return d;
}

// ---------------------------------------------------------------------------
// Fused kernel: per-CTA K/V projection of its key tile + attention partials.
// K/V key-pair packed: u64 = (val[key 2j], val[key 2j+1]) per dim.
// Bounded scores (|s_log2| < ~12) -> no max subtraction; split partials
// combine by plain addition.
// ---------------------------------------------------------------------------
__global__ void __launch_bounds__(THREADS)
attn_kernel(const float* __restrict__ x,
            const float* __restrict__ theta,
            const float* __restrict__ Wk,
            const float* __restrict__ Wv) {
    __shared__ ulonglong2 Ka[KT/2];      // (d0 pair, d1 pair) per key-pair
    __shared__ ulonglong2 Kb[KT/2];      // (d2 pair, d3 pair)
    __shared__ ulonglong2 Va[KT/2];
    __shared__ ulonglong2 Vb[KT/2];
    __shared__ float wk[DK * EE];
    __shared__ float wv[DK * EE];

    int tid = threadIdx.x;               // 0..127
    int qb  = blockIdx.x;                // 0..15
    int bh  = blockIdx.y;                // 0..15
    int ks  = blockIdx.z;                // 0..15
    int b = bh >> 2, h = bh & 3;

    if (tid < DK * EE) {
        wk[tid] = Wk[h * DK * EE + tid];
        wv[tid] = Wv[h * DK * EE + tid];
    }

    // ---- query: q = cos(x+theta) * (0.5*log2 e), duplicated-packed ----
    int sq = qb * QBLK + tid;
    const float4 thv = *reinterpret_cast<const float4*>(theta + h * DK);
    const float4 xq = *reinterpret_cast<const float4*>(x + (b * SS + sq) * EE + h * DK);
    const float SCL = 0.72134752044448170368f;   // 0.5 * log2(e)
    float c0 = cosf(xq.x + thv.x) * SCL;
    float c1 = cosf(xq.y + thv.y) * SCL;
    float c2 = cosf(xq.z + thv.z) * SCL;
    float c3 = cosf(xq.w + thv.w) * SCL;
    u64 qd0 = pk2(c0, c0), qd1 = pk2(c1, c1);
    u64 qd2 = pk2(c2, c2), qd3 = pk2(c3, c3);

    __syncthreads();

    // ---- K/V tile: thread tid (<KT/2) builds key tokens (2*tid, 2*tid+1) ----
    if (tid < KT/2) {
        float kk[2][DK], vv[2][DK];
        #pragma unroll
        for (int t = 0; t < 2; t++) {
            int tok = 2 * tid + t;
            const float4* x4 = reinterpret_cast<const float4*>(
                x + ((b * SS + ks * KT) + tok) * EE);
            float xr[EE];
            #pragma unroll
            for (int r = 0; r < 4; r++) {
                float4 q = x4[r];
                xr[4*r+0] = q.x; xr[4*r+1] = q.y; xr[4*r+2] = q.z; xr[4*r+3] = q.w;
            }
            #pragma unroll
            for (int d = 0; d < DK; d++) {
                float a = 0.f, c = 0.f;
                #pragma unroll
                for (int e = 0; e < EE; e++) {
                    a = fmaf(xr[e], wk[d * EE + e], a);
                    c = fmaf(xr[e], wv[d * EE + e], c);
                }
                kk[t][d] = a; vv[t][d] = c;
            }
        }
        ulonglong2 t0, t1;
        t0.x = pk2(kk[0][0], kk[1][0]); t0.y = pk2(kk[0][1], kk[1][1]);
        t1.x = pk2(kk[0][2], kk[1][2]); t1.y = pk2(kk[0][3], kk[1][3]);
        Ka[tid] = t0; Kb[tid] = t1;
        t0.x = pk2(vv[0][0], vv[1][0]); t0.y = pk2(vv[0][1], vv[1][1]);
        t1.x = pk2(vv[0][2], vv[1][2]); t1.y = pk2(vv[0][3], vv[1][3]);
        Va[tid] = t0; Vb[tid] = t1;
    }
    __syncthreads();

    u64 A0 = 0ULL, A1 = 0ULL, A2 = 0ULL, A3 = 0ULL, L = 0ULL;

    #pragma unroll 8
    for (int jp = 0; jp < KT/2; jp++) {
        ulonglong2 ka = Ka[jp];              // broadcast LDS.128
        ulonglong2 kb = Kb[jp];
        ulonglong2 va = Va[jp];
        ulonglong2 vb = Vb[jp];
        u64 s = mul2(qd0, ka.x);
        s = fma2(qd1, ka.y, s);
        s = fma2(qd2, kb.x, s);
        s = fma2(qd3, kb.y, s);              // (score_even, score_odd)
        float se, so; upk2(s, se, so);
        u64 pp = pk2(ex2f(se), ex2f(so));
        L  = add2(L, pp);
        A0 = fma2(pp, va.x, A0);
        A1 = fma2(pp, va.y, A1);
        A2 = fma2(pp, vb.x, A2);
        A3 = fma2(pp, vb.y, A3);
    }

    int idx = ks * PSTRIDE + (b * SS + sq) * HH + h;
    float e0, o0, e1, o1, e2, o2, e3, o3, le, lo;
    upk2(A0, e0, o0); upk2(A1, e1, o1);
    upk2(A2, e2, o2); upk2(A3, e3, o3);
    upk2(L, le, lo);
    reinterpret_cast<float4*>(g_parta)[idx] =
        make_float4(e0 + o0, e1 + o1, e2 + o2, e3 + o3);
    g_partl[idx] = le + lo;
}

// ---------------------------------------------------------------------------
// Epilogue: each (token,head) handled by TWO threads (8 splits each) so the
// load batch fits the register budget; halves combined via smem; then
// out = att @ Wc^T with Wc stored TRANSPOSED in smem (conflict-free).
// ---------------------------------------------------------------------------
#define TPB 32          // tokens per block
#define ATT_PITCH 17

__global__ void __launch_bounds__(256)
epi_kernel(const float* __restrict__ Wc, float* __restrict__ out) {
    __shared__ float wct[EE * EE];            // wct[e*16+o] = Wc[o*16+e]
    __shared__ float att[TPB * ATT_PITCH];
    __shared__ float ps[2][TPB][HH][5];       // per-half partial sums (+denom)

    int tid = threadIdx.x;                    // 0..255
    wct[(tid & 15) * EE + (tid >> 4)] = Wc[tid];

    int token0 = blockIdx.x * TPB;
    int half = tid >> 7;                      // 0/1
    int r    = tid & 127;
    int tl   = r >> 2;                        // local token 0..31
    int h    = r & 3;

    const float4* pa = reinterpret_cast<const float4*>(g_parta);
    const float*  pl = g_partl;
    int pbase = (token0 + tl) * HH + h + half * 8 * PSTRIDE;

    // 8 independent float4 + 8 scalar loads (fits in regs -> real MLP)
    float4 t0 = pa[pbase + 0*PSTRIDE], t1 = pa[pbase + 1*PSTRIDE];
    float4 t2 = pa[pbase + 2*PSTRIDE], t3 = pa[pbase + 3*PSTRIDE];
    float4 t4 = pa[pbase + 4*PSTRIDE], t5 = pa[pbase + 5*PSTRIDE];
    float4 t6 = pa[pbase + 6*PSTRIDE], t7 = pa[pbase + 7*PSTRIDE];
    float l0 = pl[pbase + 0*PSTRIDE], l1 = pl[pbase + 1*PSTRIDE];
    float l2 = pl[pbase + 2*PSTRIDE], l3 = pl[pbase + 3*PSTRIDE];
    float l4 = pl[pbase + 4*PSTRIDE], l5 = pl[pbase + 5*PSTRIDE];
    float l6 = pl[pbase + 6*PSTRIDE], l7 = pl[pbase + 7*PSTRIDE];

    t0.x += t1.x; t0.y += t1.y; t0.z += t1.z; t0.w += t1.w;
    t2.x += t3.x; t2.y += t3.y; t2.z += t3.z; t2.w += t3.w;
    t4.x += t5.x; t4.y += t5.y; t4.z += t5.z; t4.w += t5.w;
    t6.x += t7.x; t6.y += t7.y; t6.z += t7.z; t6.w += t7.w;
    t0.x += t2.x; t0.y += t2.y; t0.z += t2.z; t0.w += t2.w;
    t4.x += t6.x; t4.y += t6.y; t4.z += t6.z; t4.w += t6.w;
    t0.x += t4.x; t0.y += t4.y; t0.z += t4.z; t0.w += t4.w;
    float l = ((l0 + l1) + (l2 + l3)) + ((l4 + l5) + (l6 + l7));

    ps[half][tl][h][0] = t0.x; ps[half][tl][h][1] = t0.y;
    ps[half][tl][h][2] = t0.z; ps[half][tl][h][3] = t0.w;
    ps[half][tl][h][4] = l;
    __syncthreads();

    if (tid < 128) {
        // combine halves, normalize, write to att row
        float a0 = ps[0][tl][h][0] + ps[1][tl][h][0];
        float a1 = ps[0][tl][h][1] + ps[1][tl][h][1];
        float a2 = ps[0][tl][h][2] + ps[1][tl][h][2];
        float a3 = ps[0][tl][h][3] + ps[1][tl][h][3];
        float inv = 1.0f / (ps[0][tl][h][4] + ps[1][tl][h][4]);
        float* arow = att + tl * ATT_PITCH + h * DK;
        arow[0] = a0 * inv; arow[1] = a1 * inv;
        arow[2] = a2 * inv; arow[3] = a3 * inv;
    }
    __syncthreads();

    if (tid < 128) {
        const float* ar = att + tl * ATT_PITCH;
        float r4[4] = {0.f, 0.f, 0.f, 0.f};
        #pragma unroll
        for (int e = 0; e < EE; e++) {
            float av = ar[e];
            #pragma unroll
            for (int d = 0; d < 4; d++)
                r4[d] = fmaf(av, wct[e * EE + h * 4 + d], r4[d]);
        }
        reinterpret_cast<float4*>(out + (token0 + tl) * EE)[h] =
            make_float4(r4[0], r4[1], r4[2], r4[3]);
    }
}

// ---------------------------------------------------------------------------
extern "C" void kernel_launch(void* const* d_in, const int* in_sizes, int n_in,
                              void* d_out, int out_size) {
    const float* x     = (const float*)d_in[0];
    const float* theta = (const float*)d_in[1];
    const float* Wk    = (const float*)d_in[2];
    const float* Wv    = (const float*)d_in[3];
    const float* Wc    = (const float*)d_in[4];
    float* out = (float*)d_out;

    attn_kernel<<<dim3(SS / QBLK, NBH, KSPLIT), THREADS>>>(x, theta, Wk, Wv);
    epi_kernel<<<(BB * SS) / TPB, 256>>>(Wc, out);
}

// round 7
// speedup vs baseline: 1.3205x; 1.3205x over previous
#include <cuda_runtime.h>

// Problem constants (fixed by the reference): B=4, S=2048, E=16, H=4, D_K=4
#define BB 4
#define SS 2048
#define EE 16
#define HH 4
#define DK 4
#define NBH (BB*HH)

#define KSPLIT 16
#define KT (SS/KSPLIT)       // 128 keys per split tile
#define THREADS 128
#define QPT 4
#define QBLK (THREADS*QPT)   // 512 queries per CTA

typedef unsigned long long u64;

// Scratch (allocation-free rule: __device__ globals)
// Layout: parta[ks][h][b][sq] as float4 rows; partl[ks][h][b][sq] scalar.
__device__ float g_parta[KSPLIT * BB * SS * EE];
__device__ float g_partl[KSPLIT * BB * SS * HH];

__device__ __forceinline__ float ex2f(float x) {
    float y; asm("ex2.approx.ftz.f32 %0, %1;" : "=f"(y) : "f"(x)); return y;
}
__device__ __forceinline__ u64 pk2(float lo, float hi) {
    u64 r; asm("mov.b64 %0, {%1, %2};" : "=l"(r) : "f"(lo), "f"(hi)); return r;
}
__device__ __forceinline__ void upk2(u64 v, float& lo, float& hi) {
    asm("mov.b64 {%0, %1}, %2;" : "=f"(lo), "=f"(hi) : "l"(v));
}
__device__ __forceinline__ u64 fma2(u64 a, u64 b, u64 c) {
    u64 d; asm("fma.rn.f32x2 %0, %1, %2, %3;" : "=l"(d) : "l"(a), "l"(b), "l"(c)); return d;
}
__device__ __forceinline__ u64 mul2(u64 a, u64 b) {
    u64 d; asm("mul.rn.f32x2 %0, %1, %2;" : "=l"(d) : "l"(a), "l"(b)); return d;
}
__device__ __forceinline__ u64 add2(u64 a, u64 b) {
    u64 d; asm("add.rn.f32x2 %0, %1, %2;" : "=l"(d) : "l"(a), "l"(b)); return d;
}

// ---------------------------------------------------------------------------
// Fused kernel: per-CTA K/V projection of its key tile + attention partials.
// K/V key-pair packed: u64 = (val[key 2j], val[key 2j+1]) per dim.
// QPT=4 queries/thread for ILP across the ex2 dependency chain.
// Bounded scores (|s_log2| < ~12) -> no max subtraction.
// ---------------------------------------------------------------------------
__global__ void __launch_bounds__(THREADS)
attn_kernel(const float* __restrict__ x,
            const float* __restrict__ theta,
            const float* __restrict__ Wk,
            const float* __restrict__ Wv) {
    __shared__ ulonglong2 Ka[KT/2];      // (d0 pair, d1 pair) per key-pair
    __shared__ ulonglong2 Kb[KT/2];      // (d2 pair, d3 pair)
    __shared__ ulonglong2 Va[KT/2];
    __shared__ ulonglong2 Vb[KT/2];
    __shared__ float wk[DK * EE];
    __shared__ float wv[DK * EE];

    int tid = threadIdx.x;               // 0..127
    int qb  = blockIdx.x;                // 0..3
    int bh  = blockIdx.y;                // 0..15
    int ks  = blockIdx.z;                // 0..15
    int b = bh >> 2, h = bh & 3;

    if (tid < DK * EE) {
        wk[tid] = Wk[h * DK * EE + tid];
        wv[tid] = Wv[h * DK * EE + tid];
    }

    // ---- queries: q = cos(x+theta) * (0.5*log2 e), duplicated-packed ----
    const float4 thv = *reinterpret_cast<const float4*>(theta + h * DK);
    const float SCL = 0.72134752044448170368f;   // 0.5 * log2(e)
    u64 qd0[QPT], qd1[QPT], qd2[QPT], qd3[QPT];
    int sq0 = qb * QBLK + tid;
    #pragma unroll
    for (int qi = 0; qi < QPT; qi++) {
        int sq = sq0 + qi * THREADS;
        const float4 xq = *reinterpret_cast<const float4*>(
            x + (b * SS + sq) * EE + h * DK);
        float c0 = __cosf(xq.x + thv.x) * SCL;
        float c1 = __cosf(xq.y + thv.y) * SCL;
        float c2 = __cosf(xq.z + thv.z) * SCL;
        float c3 = __cosf(xq.w + thv.w) * SCL;
        qd0[qi] = pk2(c0, c0); qd1[qi] = pk2(c1, c1);
        qd2[qi] = pk2(c2, c2); qd3[qi] = pk2(c3, c3);
    }
    __syncthreads();

    // ---- K/V tile build: thread t<64 computes key tokens (2t, 2t+1) ----
    if (tid < KT/2) {
        float kk[2][DK], vv[2][DK];
        #pragma unroll
        for (int t = 0; t < 2; t++) {
            int tok = 2 * tid + t;
            const float4* x4 = reinterpret_cast<const float4*>(
                x + ((b * SS + ks * KT) + tok) * EE);
            float xr[EE];
            #pragma unroll
            for (int r = 0; r < 4; r++) {
                float4 q = x4[r];
                xr[4*r+0] = q.x; xr[4*r+1] = q.y; xr[4*r+2] = q.z; xr[4*r+3] = q.w;
            }
            #pragma unroll
            for (int d = 0; d < DK; d++) {
                float a = 0.f, c = 0.f;
                #pragma unroll
                for (int e = 0; e < EE; e++) {
                    a = fmaf(xr[e], wk[d * EE + e], a);
                    c = fmaf(xr[e], wv[d * EE + e], c);
                }
                kk[t][d] = a; vv[t][d] = c;
            }
        }
        ulonglong2 t0, t1;
        t0.x = pk2(kk[0][0], kk[1][0]); t0.y = pk2(kk[0][1], kk[1][1]);
        t1.x = pk2(kk[0][2], kk[1][2]); t1.y = pk2(kk[0][3], kk[1][3]);
        Ka[tid] = t0; Kb[tid] = t1;
        t0.x = pk2(vv[0][0], vv[1][0]); t0.y = pk2(vv[0][1], vv[1][1]);
        t1.x = pk2(vv[0][2], vv[1][2]); t1.y = pk2(vv[0][3], vv[1][3]);
        Va[tid] = t0; Vb[tid] = t1;
    }
    __syncthreads();

    u64 A0[QPT], A1[QPT], A2[QPT], A3[QPT], L[QPT];
    #pragma unroll
    for (int qi = 0; qi < QPT; qi++) {
        A0[qi] = 0ULL; A1[qi] = 0ULL; A2[qi] = 0ULL; A3[qi] = 0ULL; L[qi] = 0ULL;
    }

    #pragma unroll 4
    for (int jp = 0; jp < KT/2; jp++) {
        ulonglong2 ka = Ka[jp];              // broadcast LDS.128
        ulonglong2 kb = Kb[jp];
        ulonglong2 va = Va[jp];
        ulonglong2 vb = Vb[jp];
        #pragma unroll
        for (int qi = 0; qi < QPT; qi++) {
            u64 s = mul2(qd0[qi], ka.x);
            s = fma2(qd1[qi], ka.y, s);
            s = fma2(qd2[qi], kb.x, s);
            s = fma2(qd3[qi], kb.y, s);       // (score_even, score_odd)
            float se, so; upk2(s, se, so);
            u64 pp = pk2(ex2f(se), ex2f(so));
            L[qi]  = add2(L[qi], pp);
            A0[qi] = fma2(pp, va.x, A0[qi]);
            A1[qi] = fma2(pp, va.y, A1[qi]);
            A2[qi] = fma2(pp, vb.x, A2[qi]);
            A3[qi] = fma2(pp, vb.y, A3[qi]);
        }
    }

    // coalesced partial stores: [ks][h][b][sq]
    int rowbase = ((ks * HH + h) * BB + b) * SS;
    #pragma unroll
    for (int qi = 0; qi < QPT; qi++) {
        int sq = sq0 + qi * THREADS;
        int idx = rowbase + sq;
        float e0, o0, e1, o1, e2, o2, e3, o3, le, lo;
        upk2(A0[qi], e0, o0); upk2(A1[qi], e1, o1);
        upk2(A2[qi], e2, o2); upk2(A3[qi], e3, o3);
        upk2(L[qi], le, lo);
        reinterpret_cast<float4*>(g_parta)[idx] =
            make_float4(e0 + o0, e1 + o1, e2 + o2, e3 + o3);
        g_partl[idx] = le + lo;
    }
}

// ---------------------------------------------------------------------------
// Epilogue: thread = (token-head, split). One float4 + one float load per
// thread (terminal loads -> guaranteed in flight), butterfly shuffle-reduce
// over the 16 splits (lane bits 0..3), normalize, then 16 threads/CTA do
// out = att @ Wc^T with transposed Wc in smem.
// ---------------------------------------------------------------------------
#define EPI_THREADS 256      // 16 token-heads (= 4 tokens) per CTA

__global__ void __launch_bounds__(EPI_THREADS)
epi_kernel(const float* __restrict__ Wc, float* __restrict__ out) {
    __shared__ float wct[EE * EE];            // wct[e*16+o] = Wc[o*16+e]
    __shared__ float att[4][EE + 1];

    int tid = threadIdx.x;                    // 0..255
    wct[(tid & 15) * EE + (tid >> 4)] = Wc[tid];

    int s        = tid & 15;                  // split
    int th_local = ((tid >> 5) << 1) | ((tid >> 4) & 1);   // 0..15
    int th_glob  = blockIdx.x * 16 + th_local;
    int tokg     = th_glob >> 2;              // global token
    int h        = th_glob & 3;
    int b        = tokg >> 11;
    int sq       = tokg & (SS - 1);

    int idx = ((s * HH + h) * BB + b) * SS + sq;
    float4 a = reinterpret_cast<const float4*>(g_parta)[idx];
    float  l = g_partl[idx];

    #pragma unroll
    for (int m = 1; m <= 8; m <<= 1) {
        a.x += __shfl_xor_sync(0xffffffffu, a.x, m);
        a.y += __shfl_xor_sync(0xffffffffu, a.y, m);
        a.z += __shfl_xor_sync(0xffffffffu, a.z, m);
        a.w += __shfl_xor_sync(0xffffffffu, a.w, m);
        l   += __shfl_xor_sync(0xffffffffu, l,   m);
    }

    if (s == 0) {
        float inv = 1.0f / l;
        int tl = th_local >> 2;
        float* arow = att[tl] + h * DK;
        arow[0] = a.x * inv; arow[1] = a.y * inv;
        arow[2] = a.z * inv; arow[3] = a.w * inv;
    }
    __syncthreads();

    if (tid < 16) {
        int tl = tid >> 2, q = tid & 3;
        const float* ar = att[tl];
        float r[4] = {0.f, 0.f, 0.f, 0.f};
        #pragma unroll
        for (int e = 0; e < EE; e++) {
            float av = ar[e];
            #pragma unroll
            for (int d = 0; d < 4; d++)
                r[d] = fmaf(av, wct[e * EE + q * 4 + d], r[d]);
        }
        int tok = blockIdx.x * 4 + tl;
        reinterpret_cast<float4*>(out + tok * EE)[q] =
            make_float4(r[0], r[1], r[2], r[3]);
    }
}

// ---------------------------------------------------------------------------
extern "C" void kernel_launch(void* const* d_in, const int* in_sizes, int n_in,
                              void* d_out, int out_size) {
    const float* x     = (const float*)d_in[0];
    const float* theta = (const float*)d_in[1];
    const float* Wk    = (const float*)d_in[2];
    const float* Wv    = (const float*)d_in[3];
    const float* Wc    = (const float*)d_in[4];
    float* out = (float*)d_out;

    attn_kernel<<<dim3(SS / QBLK, NBH, KSPLIT), THREADS>>>(x, theta, Wk, Wv);
    epi_kernel<<<(BB * SS) / 4, EPI_THREADS>>>(Wc, out);
}